// round 14
// baseline (speedup 1.0000x reference)
#include <cuda_runtime.h>
#include <cuda_bf16.h>
#include <cstdint>

constexpr int BH = 16, S = 2048, D = 64;

__device__ float g_sums[BH * S];

// ---------------- helpers ----------------
__device__ __forceinline__ uint32_t smem_u32(const void* p) {
    uint32_t a;
    asm("{ .reg .u64 t; cvta.to.shared.u64 t, %1; cvt.u32.u64 %0, t; }" : "=r"(a) : "l"(p));
    return a;
}
__device__ __forceinline__ uint32_t pk(float a, float b) {
    __nv_bfloat162 t = __floats2bfloat162_rn(a, b);
    return *reinterpret_cast<uint32_t*>(&t);
}
__device__ __forceinline__ float hi_bf(float x) {
    return __bfloat162float(__float2bfloat16_rn(x));
}
__device__ __forceinline__ uint32_t sw128(uint32_t b) { return b ^ ((b >> 3) & 0x70); }

__device__ __forceinline__ void ldsm4(uint32_t a, uint32_t r[4]) {
    asm volatile("ldmatrix.sync.aligned.m8n8.x4.shared.b16 {%0,%1,%2,%3}, [%4];"
                 : "=r"(r[0]), "=r"(r[1]), "=r"(r[2]), "=r"(r[3]) : "r"(a));
}
__device__ __forceinline__ void ldsm4t(uint32_t a, uint32_t r[4]) {
    asm volatile("ldmatrix.sync.aligned.m8n8.x4.trans.shared.b16 {%0,%1,%2,%3}, [%4];"
                 : "=r"(r[0]), "=r"(r[1]), "=r"(r[2]), "=r"(r[3]) : "r"(a));
}
__device__ __forceinline__ void mma16816(float c[4], const uint32_t a[4], uint32_t b0, uint32_t b1) {
    asm volatile(
        "mma.sync.aligned.m16n8k16.row.col.f32.bf16.bf16.f32 "
        "{%0,%1,%2,%3}, {%4,%5,%6,%7}, {%8,%9}, {%0,%1,%2,%3};"
        : "+f"(c[0]), "+f"(c[1]), "+f"(c[2]), "+f"(c[3])
        : "r"(a[0]), "r"(a[1]), "r"(a[2]), "r"(a[3]), "r"(b0), "r"(b1));
}
// streaming (evict-first) float2 store: e is not re-read within L2 lifetime
__device__ __forceinline__ void stcs2(float* p, float a, float b) {
    asm volatile("st.global.cs.v2.f32 [%0], {%1, %2};" :: "l"(p), "f"(a), "f"(b) : "memory");
}

// smem map (bytes): Qhi 16K, Qlo 16K, Khi 16K, Klo 16K, Vhi 16K, Vlo 16K, sums 512
constexpr int QHI = 0, QLO = 16384, KHI = 32768, KLO = 49152,
              VHI = 65536, VLO = 81920, SUMO = 98304, OBUF = 32768;
constexpr size_t SMEM_F = 98816;   // 2 CTAs/SM -> 32 warps

// ==== fused: e = exp(clip/mask/decay(QK^T)) -> p region, O = (e@V)*inv ====
__global__ void __launch_bounds__(512, 2)
fused_kernel(const float* __restrict__ Q, const float* __restrict__ K,
             const float* __restrict__ V, const int* __restrict__ mask,
             const float* __restrict__ decay, float* __restrict__ e_out,
             float* __restrict__ out_o)
{
    extern __shared__ char sm[];
    const uint32_t sb = smem_u32(sm);
    const int t = threadIdx.x, wid = t >> 5, lane = t & 31;
    const int bid = blockIdx.x, bh = bid >> 4, q0 = (bid & 15) * 128, b = bh >> 3;

    // stage Q tile [128 q][64 d] (pre-scaled 1/8) -> hi/lo bf16
    {
        const float4* Qp = (const float4*)(Q + ((size_t)bh * S + q0) * D);
        #pragma unroll
        for (int i = 0; i < 4; ++i) {
            int idx = t + i * 512, r = idx >> 4, c4 = (idx & 15) * 4;
            float4 v = Qp[idx];
            float x0 = v.x * 0.125f, x1 = v.y * 0.125f, x2 = v.z * 0.125f, x3 = v.w * 0.125f;
            float h0 = hi_bf(x0), h1 = hi_bf(x1), h2 = hi_bf(x2), h3 = hi_bf(x3);
            uint32_t o = sw128((uint32_t)(r * 128 + c4 * 2));
            *(uint2*)(sm + QHI + o) = make_uint2(pk(h0, h1), pk(h2, h3));
            *(uint2*)(sm + QLO + o) = make_uint2(pk(x0 - h0, x1 - h1), pk(x2 - h2, x3 - h3));
        }
    }

    const int wm = wid & 7;        // m16 block (q rows), 8 blocks = 128 rows
    const int wn = wid >> 3;       // 64-col half of the 128-col kv tile
    const int r0 = wm * 16 + (lane >> 2), r1 = r0 + 8;
    const size_t gq0 = (size_t)bh * S + q0;
    const float* drow0 = decay + (gq0 + r0) * S;
    const float* drow1 = decay + (gq0 + r1) * S;
    const int*   mrow0 = mask + ((size_t)b * S + q0 + r0) * S;
    const int*   mrow1 = mask + ((size_t)b * S + q0 + r1) * S;
    float*       erow0 = e_out + (gq0 + r0) * S;
    float*       erow1 = e_out + (gq0 + r1) * S;
    float sum0 = 0.f, sum1 = 0.f;

    float oacc[8][4];
    #pragma unroll
    for (int n = 0; n < 8; ++n)
        #pragma unroll
        for (int j = 0; j < 4; ++j) oacc[n][j] = 0.f;

    for (int it = 0; it < 16; ++it) {
        __syncthreads();
        // stage K,V tiles [128 kv][64 d] -> hi/lo bf16
        {
            const float4* Kp = (const float4*)(K + ((size_t)bh * S + it * 128) * D);
            const float4* Vp = (const float4*)(V + ((size_t)bh * S + it * 128) * D);
            #pragma unroll
            for (int i = 0; i < 4; ++i) {
                int idx = t + i * 512, r = idx >> 4, c4 = (idx & 15) * 4;
                uint32_t o = sw128((uint32_t)(r * 128 + c4 * 2));
                float4 v = Kp[idx];
                float h0 = hi_bf(v.x), h1 = hi_bf(v.y), h2 = hi_bf(v.z), h3 = hi_bf(v.w);
                *(uint2*)(sm + KHI + o) = make_uint2(pk(h0, h1), pk(h2, h3));
                *(uint2*)(sm + KLO + o) = make_uint2(pk(v.x - h0, v.y - h1), pk(v.z - h2, v.w - h3));
                float4 w = Vp[idx];
                float g0 = hi_bf(w.x), g1 = hi_bf(w.y), g2 = hi_bf(w.z), g3 = hi_bf(w.w);
                *(uint2*)(sm + VHI + o) = make_uint2(pk(g0, g1), pk(g2, g3));
                *(uint2*)(sm + VLO + o) = make_uint2(pk(w.x - g0, w.y - g1), pk(w.z - g2, w.w - g3));
            }
        }

        // prefetch decay + mask for this tile (consumed post-MMA)
        const int cb0 = it * 128 + wn * 64 + (lane & 3) * 2;
        float dpr[32];
        uint32_t mbits = 0;
        #pragma unroll
        for (int nt = 0; nt < 8; ++nt) {
            const int c = cb0 + nt * 8;
            float2 d0 = *(const float2*)(drow0 + c);
            float2 d1 = *(const float2*)(drow1 + c);
            int2   m0 = *(const int2*)(mrow0 + c);
            int2   m1 = *(const int2*)(mrow1 + c);
            dpr[nt * 4 + 0] = d0.x; dpr[nt * 4 + 1] = d0.y;
            dpr[nt * 4 + 2] = d1.x; dpr[nt * 4 + 3] = d1.y;
            uint32_t g = (m0.x ? 1u : 0u) | (m0.y ? 2u : 0u) |
                         (m1.x ? 4u : 0u) | (m1.y ? 8u : 0u);
            mbits |= g << (nt * 4);
        }
        __syncthreads();

        // ---------------- S = QK^T (3-split) ----------------
        float acc[8][4];
        #pragma unroll
        for (int n = 0; n < 8; ++n)
            #pragma unroll
            for (int j = 0; j < 4; ++j) acc[n][j] = 0.f;

        #pragma unroll
        for (int kc4 = 0; kc4 < 4; ++kc4) {
            const int kc = kc4 * 16;
            const uint32_t arow = (uint32_t)((wm * 16 + (lane & 15)) * 128 +
                                             (kc + ((lane >> 4) & 1) * 8) * 2);
            uint32_t ah[4], al[4];
            ldsm4(sb + QHI + sw128(arow), ah);
            #pragma unroll
            for (int p = 0; p < 4; ++p) {
                uint32_t brow = (uint32_t)((wn * 64 + p * 16 + (lane & 7) + (lane >> 4) * 8) * 128 +
                                           (kc + ((lane >> 3) & 1) * 8) * 2);
                uint32_t bo = sw128(brow);
                uint32_t bb[4];
                ldsm4(sb + KHI + bo, bb);
                mma16816(acc[2 * p], ah, bb[0], bb[1]);
                mma16816(acc[2 * p + 1], ah, bb[2], bb[3]);
                ldsm4(sb + KLO + bo, bb);
                mma16816(acc[2 * p], ah, bb[0], bb[1]);
                mma16816(acc[2 * p + 1], ah, bb[2], bb[3]);
            }
            ldsm4(sb + QLO + sw128(arow), al);
            #pragma unroll
            for (int p = 0; p < 4; ++p) {
                uint32_t brow = (uint32_t)((wn * 64 + p * 16 + (lane & 7) + (lane >> 4) * 8) * 128 +
                                           (kc + ((lane >> 3) & 1) * 8) * 2);
                uint32_t bb[4];
                ldsm4(sb + KHI + sw128(brow), bb);
                mma16816(acc[2 * p], al, bb[0], bb[1]);
                mma16816(acc[2 * p + 1], al, bb[2], bb[3]);
            }
        }

        // ---------------- epilogue: clip/mask/decay/exp (prefetched operands) ----------------
        #pragma unroll
        for (int nt = 0; nt < 8; ++nt) {
            const int c = cb0 + nt * 8;
            float s00 = fminf(fmaxf(acc[nt][0], 1e-9f), 1e9f);
            float s01 = fminf(fmaxf(acc[nt][1], 1e-9f), 1e9f);
            float s10 = fminf(fmaxf(acc[nt][2], 1e-9f), 1e9f);
            float s11 = fminf(fmaxf(acc[nt][3], 1e-9f), 1e9f);
            s00 = (mbits >> (nt * 4) & 1u) ? s00 : -1e9f;
            s01 = (mbits >> (nt * 4) & 2u) ? s01 : -1e9f;
            s10 = (mbits >> (nt * 4) & 4u) ? s10 : -1e9f;
            s11 = (mbits >> (nt * 4) & 8u) ? s11 : -1e9f;
            float e00 = __expf(s00 * dpr[nt * 4 + 0]), e01 = __expf(s01 * dpr[nt * 4 + 1]);
            float e10 = __expf(s10 * dpr[nt * 4 + 2]), e11 = __expf(s11 * dpr[nt * 4 + 3]);
            sum0 += e00 + e01;
            sum1 += e10 + e11;
            stcs2(erow0 + c, e00, e01);
            stcs2(erow1 + c, e10, e11);
            acc[nt][0] = e00; acc[nt][1] = e01; acc[nt][2] = e10; acc[nt][3] = e11;
        }

        // ---------------- PV: O += e @ V (A recycled from accumulators) ----------------
        #pragma unroll
        for (int kc = 0; kc < 4; ++kc) {
            float h00 = hi_bf(acc[2*kc][0]),   h01 = hi_bf(acc[2*kc][1]);
            float h02 = hi_bf(acc[2*kc][2]),   h03 = hi_bf(acc[2*kc][3]);
            float h10 = hi_bf(acc[2*kc+1][0]), h11 = hi_bf(acc[2*kc+1][1]);
            float h12 = hi_bf(acc[2*kc+1][2]), h13 = hi_bf(acc[2*kc+1][3]);
            uint32_t ah[4] = { pk(h00, h01), pk(h02, h03), pk(h10, h11), pk(h12, h13) };
            uint32_t al[4] = { pk(acc[2*kc][0] - h00,   acc[2*kc][1] - h01),
                               pk(acc[2*kc][2] - h02,   acc[2*kc][3] - h03),
                               pk(acc[2*kc+1][0] - h10, acc[2*kc+1][1] - h11),
                               pk(acc[2*kc+1][2] - h12, acc[2*kc+1][3] - h13) };
            #pragma unroll
            for (int p2 = 0; p2 < 4; ++p2) {
                uint32_t brow = (uint32_t)((wn * 64 + kc * 16 + (lane & 7) + ((lane >> 3) & 1) * 8) * 128 +
                                           (p2 * 16 + (lane >> 4) * 8) * 2);
                uint32_t bo = sw128(brow);
                uint32_t bb[4];
                ldsm4t(sb + VHI + bo, bb);
                mma16816(oacc[2 * p2],     ah, bb[0], bb[1]);
                mma16816(oacc[2 * p2 + 1], ah, bb[2], bb[3]);
                mma16816(oacc[2 * p2],     al, bb[0], bb[1]);
                mma16816(oacc[2 * p2 + 1], al, bb[2], bb[3]);
                ldsm4t(sb + VLO + bo, bb);
                mma16816(oacc[2 * p2],     ah, bb[0], bb[1]);
                mma16816(oacc[2 * p2 + 1], ah, bb[2], bb[3]);
            }
        }
    }

    // ---------------- row sums -> g_sums ----------------
    #pragma unroll
    for (int o = 1; o <= 2; o <<= 1) {
        sum0 += __shfl_xor_sync(0xffffffffu, sum0, o);
        sum1 += __shfl_xor_sync(0xffffffffu, sum1, o);
    }
    float* sbuf = (float*)(sm + SUMO);
    __syncthreads();
    if (wn == 0 && (lane & 3) == 0) { sbuf[r0] = sum0; sbuf[r1] = sum1; }
    __syncthreads();
    if (wn == 1 && (lane & 3) == 0) {
        float t0 = sbuf[r0] + sum0, t1 = sbuf[r1] + sum1;
        sbuf[r0] = t0; sbuf[r1] = t1;
        g_sums[gq0 + r0] = t0;
        g_sums[gq0 + r1] = t1;
    }
    __syncthreads();

    // ---------------- O: reduce across the two kv-half warps, scale, store ----------------
    float* ob = (float*)(sm + OBUF);   // [128][64], reuses K staging space (32KB)
    const int cc = (lane & 3) * 2;
    if (wn == 0) {
        #pragma unroll
        for (int nt = 0; nt < 8; ++nt) {
            ob[r0 * 64 + nt * 8 + cc]     = oacc[nt][0];
            ob[r0 * 64 + nt * 8 + cc + 1] = oacc[nt][1];
            ob[r1 * 64 + nt * 8 + cc]     = oacc[nt][2];
            ob[r1 * 64 + nt * 8 + cc + 1] = oacc[nt][3];
        }
    }
    __syncthreads();
    if (wn == 1) {
        float iv0 = 1.f / sbuf[r0], iv1 = 1.f / sbuf[r1];
        float* o0 = out_o + (gq0 + r0) * D;
        float* o1 = out_o + (gq0 + r1) * D;
        #pragma unroll
        for (int nt = 0; nt < 8; ++nt) {
            int c = nt * 8 + cc;
            *(float2*)(o0 + c) = make_float2((oacc[nt][0] + ob[r0 * 64 + c]) * iv0,
                                             (oacc[nt][1] + ob[r0 * 64 + c + 1]) * iv0);
            *(float2*)(o1 + c) = make_float2((oacc[nt][2] + ob[r1 * 64 + c]) * iv1,
                                             (oacc[nt][3] + ob[r1 * 64 + c + 1]) * iv1);
        }
    }
}

// ============ rescale: p = e * inv[row], in place (streaming) ============
__global__ void __launch_bounds__(256)
rescale_kernel(float* __restrict__ p)
{
    const int row = blockIdx.x * 2 + (threadIdx.x >> 7);
    const float inv = 1.f / g_sums[row];
    float4* pr = (float4*)(p + (size_t)row * S);
    const int c = threadIdx.x & 127;
    #pragma unroll
    for (int i = 0; i < 4; ++i) {
        float4 v = __ldcs(pr + c + i * 128);
        v.x *= inv; v.y *= inv; v.z *= inv; v.w *= inv;
        __stcs(pr + c + i * 128, v);
    }
}

extern "C" void kernel_launch(void* const* d_in, const int* in_sizes, int n_in,
                              void* d_out, int out_size)
{
    const float* Q     = (const float*)d_in[0];
    const float* K     = (const float*)d_in[1];
    const float* V     = (const float*)d_in[2];
    const int*   mask  = (const int*)d_in[3];
    const float* decay = (const float*)d_in[4];

    float* out_o = (float*)d_out;
    float* out_p = (float*)d_out + (size_t)BH * S * D;

    cudaFuncSetAttribute(fused_kernel, cudaFuncAttributeMaxDynamicSharedMemorySize, (int)SMEM_F);

    fused_kernel<<<BH * (S / 128), 512, SMEM_F>>>(Q, K, V, mask, decay, out_p, out_o);
    rescale_kernel<<<BH * S / 2, 256>>>(out_p);
}

// round 15
// speedup vs baseline: 1.2148x; 1.2148x over previous
#include <cuda_runtime.h>
#include <cuda_bf16.h>
#include <cstdint>

constexpr int BH = 16, S = 2048, D = 64;

__device__ float g_sums[BH * S];
__device__ uint32_t g_maskbits[2 * S * (S / 32)];   // 1 MB packed mask

// ---------------- helpers ----------------
__device__ __forceinline__ uint32_t smem_u32(const void* p) {
    uint32_t a;
    asm("{ .reg .u64 t; cvta.to.shared.u64 t, %1; cvt.u32.u64 %0, t; }" : "=r"(a) : "l"(p));
    return a;
}
__device__ __forceinline__ uint32_t pk(float a, float b) {
    __nv_bfloat162 t = __floats2bfloat162_rn(a, b);
    return *reinterpret_cast<uint32_t*>(&t);
}
__device__ __forceinline__ float hi_bf(float x) {
    return __bfloat162float(__float2bfloat16_rn(x));
}
__device__ __forceinline__ uint32_t sw128(uint32_t b) { return b ^ ((b >> 3) & 0x70); }

__device__ __forceinline__ void ldsm4(uint32_t a, uint32_t r[4]) {
    asm volatile("ldmatrix.sync.aligned.m8n8.x4.shared.b16 {%0,%1,%2,%3}, [%4];"
                 : "=r"(r[0]), "=r"(r[1]), "=r"(r[2]), "=r"(r[3]) : "r"(a));
}
__device__ __forceinline__ void ldsm4t(uint32_t a, uint32_t r[4]) {
    asm volatile("ldmatrix.sync.aligned.m8n8.x4.trans.shared.b16 {%0,%1,%2,%3}, [%4];"
                 : "=r"(r[0]), "=r"(r[1]), "=r"(r[2]), "=r"(r[3]) : "r"(a));
}
__device__ __forceinline__ void mma16816(float c[4], const uint32_t a[4], uint32_t b0, uint32_t b1) {
    asm volatile(
        "mma.sync.aligned.m16n8k16.row.col.f32.bf16.bf16.f32 "
        "{%0,%1,%2,%3}, {%4,%5,%6,%7}, {%8,%9}, {%0,%1,%2,%3};"
        : "+f"(c[0]), "+f"(c[1]), "+f"(c[2]), "+f"(c[3])
        : "r"(a[0]), "r"(a[1]), "r"(a[2]), "r"(a[3]), "r"(b0), "r"(b1));
}
// streaming (evict-first) float2 store: e is not re-read within L2 lifetime
__device__ __forceinline__ void stcs2(float* p, float a, float b) {
    asm volatile("st.global.cs.v2.f32 [%0], {%1, %2};" :: "l"(p), "f"(a), "f"(b) : "memory");
}

// smem map (bytes): Qhi 8K, Qlo 8K, Khi 16K, Klo 16K, Vhi 16K, Vlo 16K, sums 256
constexpr int QHI = 0, QLO = 8192, KHI = 16384, KLO = 32768,
              VHI = 49152, VLO = 65536, SUMO = 81920, OBUF = 16384;
constexpr size_t SMEM_F = 82432;

// ============ pack mask int32 -> bits (one-time, ~67MB traffic) ============
__global__ void __launch_bounds__(256)
pack_mask_kernel(const int* __restrict__ mask)
{
    const int tid = blockIdx.x * 256 + threadIdx.x;
    const uint32_t bal = __ballot_sync(0xffffffffu, mask[tid] != 0);
    if ((threadIdx.x & 31) == 0) g_maskbits[tid >> 5] = bal;
}

// ==== fused: e = exp(clip/mask/decay(QK^T)) -> p region, O = (e@V)*inv ====
__global__ void __launch_bounds__(256, 2)
fused_kernel(const float* __restrict__ Q, const float* __restrict__ K,
             const float* __restrict__ V, const float* __restrict__ decay,
             float* __restrict__ e_out, float* __restrict__ out_o)
{
    extern __shared__ char sm[];
    const uint32_t sb = smem_u32(sm);
    const int t = threadIdx.x, wid = t >> 5, lane = t & 31;
    const int bid = blockIdx.x, bh = bid >> 5, q0 = (bid & 31) * 64, b = bh >> 3;

    // stage Q tile (pre-scaled 1/8) -> hi/lo bf16
    {
        const float4* Qp = (const float4*)(Q + ((size_t)bh * S + q0) * D);
        #pragma unroll
        for (int i = 0; i < 4; ++i) {
            int idx = t + i * 256, r = idx >> 4, c4 = (idx & 15) * 4;
            float4 v = Qp[idx];
            float x0 = v.x * 0.125f, x1 = v.y * 0.125f, x2 = v.z * 0.125f, x3 = v.w * 0.125f;
            float h0 = hi_bf(x0), h1 = hi_bf(x1), h2 = hi_bf(x2), h3 = hi_bf(x3);
            uint32_t o = sw128((uint32_t)(r * 128 + c4 * 2));
            *(uint2*)(sm + QHI + o) = make_uint2(pk(h0, h1), pk(h2, h3));
            *(uint2*)(sm + QLO + o) = make_uint2(pk(x0 - h0, x1 - h1), pk(x2 - h2, x3 - h3));
        }
    }

    const int wm = wid & 3;        // m16 block (q rows)
    const int wn = wid >> 2;       // 64-col half of the 128-col kv tile
    const int r0 = wm * 16 + (lane >> 2), r1 = r0 + 8;
    const size_t gq0 = (size_t)bh * S + q0;
    const float* drow0 = decay + (gq0 + r0) * S;
    const float* drow1 = decay + (gq0 + r1) * S;
    const uint32_t* mbr0 = g_maskbits + ((size_t)b * S + q0 + r0) * (S / 32);
    const uint32_t* mbr1 = g_maskbits + ((size_t)b * S + q0 + r1) * (S / 32);
    float*       erow0 = e_out + (gq0 + r0) * S;
    float*       erow1 = e_out + (gq0 + r1) * S;
    float sum0 = 0.f, sum1 = 0.f;

    float oacc[8][4];
    #pragma unroll
    for (int n = 0; n < 8; ++n)
        #pragma unroll
        for (int j = 0; j < 4; ++j) oacc[n][j] = 0.f;

    for (int it = 0; it < 16; ++it) {
        __syncthreads();
        // stage K,V tiles [128 kv][64 d] -> hi/lo bf16
        {
            const float4* Kp = (const float4*)(K + ((size_t)bh * S + it * 128) * D);
            const float4* Vp = (const float4*)(V + ((size_t)bh * S + it * 128) * D);
            #pragma unroll
            for (int i = 0; i < 8; ++i) {
                int idx = t + i * 256, r = idx >> 4, c4 = (idx & 15) * 4;
                uint32_t o = sw128((uint32_t)(r * 128 + c4 * 2));
                float4 v = Kp[idx];
                float h0 = hi_bf(v.x), h1 = hi_bf(v.y), h2 = hi_bf(v.z), h3 = hi_bf(v.w);
                *(uint2*)(sm + KHI + o) = make_uint2(pk(h0, h1), pk(h2, h3));
                *(uint2*)(sm + KLO + o) = make_uint2(pk(v.x - h0, v.y - h1), pk(v.z - h2, v.w - h3));
                float4 w = Vp[idx];
                float g0 = hi_bf(w.x), g1 = hi_bf(w.y), g2 = hi_bf(w.z), g3 = hi_bf(w.w);
                *(uint2*)(sm + VHI + o) = make_uint2(pk(g0, g1), pk(g2, g3));
                *(uint2*)(sm + VLO + o) = make_uint2(pk(w.x - g0, w.y - g1), pk(w.z - g2, w.w - g3));
            }
        }

        // prefetch decay + packed mask words for this tile (consumed post-MMA)
        const int cb0 = it * 128 + wn * 64 + (lane & 3) * 2;
        const int wbase = (it * 128 + wn * 64) >> 5;     // 2 words per row cover 64 cols
        const uint32_t w00 = mbr0[wbase], w01 = mbr0[wbase + 1];
        const uint32_t w10 = mbr1[wbase], w11 = mbr1[wbase + 1];
        float dpr[32];
        #pragma unroll
        for (int nt = 0; nt < 8; ++nt) {
            const int c = cb0 + nt * 8;
            float2 d0 = *(const float2*)(drow0 + c);
            float2 d1 = *(const float2*)(drow1 + c);
            dpr[nt * 4 + 0] = d0.x; dpr[nt * 4 + 1] = d0.y;
            dpr[nt * 4 + 2] = d1.x; dpr[nt * 4 + 3] = d1.y;
        }
        __syncthreads();

        // ---------------- S = QK^T (3-split) ----------------
        float acc[8][4];
        #pragma unroll
        for (int n = 0; n < 8; ++n)
            #pragma unroll
            for (int j = 0; j < 4; ++j) acc[n][j] = 0.f;

        #pragma unroll
        for (int kc4 = 0; kc4 < 4; ++kc4) {
            const int kc = kc4 * 16;
            const uint32_t arow = (uint32_t)((wm * 16 + (lane & 15)) * 128 +
                                             (kc + ((lane >> 4) & 1) * 8) * 2);
            uint32_t ah[4], al[4];
            ldsm4(sb + QHI + sw128(arow), ah);
            #pragma unroll
            for (int p = 0; p < 4; ++p) {
                uint32_t brow = (uint32_t)((wn * 64 + p * 16 + (lane & 7) + (lane >> 4) * 8) * 128 +
                                           (kc + ((lane >> 3) & 1) * 8) * 2);
                uint32_t bo = sw128(brow);
                uint32_t bb[4];
                ldsm4(sb + KHI + bo, bb);
                mma16816(acc[2 * p], ah, bb[0], bb[1]);
                mma16816(acc[2 * p + 1], ah, bb[2], bb[3]);
                ldsm4(sb + KLO + bo, bb);
                mma16816(acc[2 * p], ah, bb[0], bb[1]);
                mma16816(acc[2 * p + 1], ah, bb[2], bb[3]);
            }
            ldsm4(sb + QLO + sw128(arow), al);
            #pragma unroll
            for (int p = 0; p < 4; ++p) {
                uint32_t brow = (uint32_t)((wn * 64 + p * 16 + (lane & 7) + (lane >> 4) * 8) * 128 +
                                           (kc + ((lane >> 3) & 1) * 8) * 2);
                uint32_t bb[4];
                ldsm4(sb + KHI + sw128(brow), bb);
                mma16816(acc[2 * p], al, bb[0], bb[1]);
                mma16816(acc[2 * p + 1], al, bb[2], bb[3]);
            }
        }

        // ---------------- epilogue: clip/mask/decay/exp (bit-packed mask) ----------------
        #pragma unroll
        for (int nt = 0; nt < 8; ++nt) {
            const int c = cb0 + nt * 8;
            const int sh = (lane & 3) * 2 + (nt & 3) * 8;   // bit pos within word
            const uint32_t wr0 = (nt < 4) ? w00 : w01;
            const uint32_t wr1 = (nt < 4) ? w10 : w11;
            float s00 = fminf(fmaxf(acc[nt][0], 1e-9f), 1e9f);
            float s01 = fminf(fmaxf(acc[nt][1], 1e-9f), 1e9f);
            float s10 = fminf(fmaxf(acc[nt][2], 1e-9f), 1e9f);
            float s11 = fminf(fmaxf(acc[nt][3], 1e-9f), 1e9f);
            s00 = (wr0 >> sh & 1u)       ? s00 : -1e9f;
            s01 = (wr0 >> (sh + 1) & 1u) ? s01 : -1e9f;
            s10 = (wr1 >> sh & 1u)       ? s10 : -1e9f;
            s11 = (wr1 >> (sh + 1) & 1u) ? s11 : -1e9f;
            float e00 = __expf(s00 * dpr[nt * 4 + 0]), e01 = __expf(s01 * dpr[nt * 4 + 1]);
            float e10 = __expf(s10 * dpr[nt * 4 + 2]), e11 = __expf(s11 * dpr[nt * 4 + 3]);
            sum0 += e00 + e01;
            sum1 += e10 + e11;
            stcs2(erow0 + c, e00, e01);
            stcs2(erow1 + c, e10, e11);
            acc[nt][0] = e00; acc[nt][1] = e01; acc[nt][2] = e10; acc[nt][3] = e11;
        }

        // ---------------- PV: O += e @ V (A recycled from accumulators) ----------------
        #pragma unroll
        for (int kc = 0; kc < 4; ++kc) {
            float h00 = hi_bf(acc[2*kc][0]),   h01 = hi_bf(acc[2*kc][1]);
            float h02 = hi_bf(acc[2*kc][2]),   h03 = hi_bf(acc[2*kc][3]);
            float h10 = hi_bf(acc[2*kc+1][0]), h11 = hi_bf(acc[2*kc+1][1]);
            float h12 = hi_bf(acc[2*kc+1][2]), h13 = hi_bf(acc[2*kc+1][3]);
            uint32_t ah[4] = { pk(h00, h01), pk(h02, h03), pk(h10, h11), pk(h12, h13) };
            uint32_t al[4] = { pk(acc[2*kc][0] - h00,   acc[2*kc][1] - h01),
                               pk(acc[2*kc][2] - h02,   acc[2*kc][3] - h03),
                               pk(acc[2*kc+1][0] - h10, acc[2*kc+1][1] - h11),
                               pk(acc[2*kc+1][2] - h12, acc[2*kc+1][3] - h13) };
            #pragma unroll
            for (int p2 = 0; p2 < 4; ++p2) {
                uint32_t brow = (uint32_t)((wn * 64 + kc * 16 + (lane & 7) + ((lane >> 3) & 1) * 8) * 128 +
                                           (p2 * 16 + (lane >> 4) * 8) * 2);
                uint32_t bo = sw128(brow);
                uint32_t bb[4];
                ldsm4t(sb + VHI + bo, bb);
                mma16816(oacc[2 * p2],     ah, bb[0], bb[1]);
                mma16816(oacc[2 * p2 + 1], ah, bb[2], bb[3]);
                mma16816(oacc[2 * p2],     al, bb[0], bb[1]);
                mma16816(oacc[2 * p2 + 1], al, bb[2], bb[3]);
                ldsm4t(sb + VLO + bo, bb);
                mma16816(oacc[2 * p2],     ah, bb[0], bb[1]);
                mma16816(oacc[2 * p2 + 1], ah, bb[2], bb[3]);
            }
        }
    }

    // ---------------- row sums -> g_sums ----------------
    #pragma unroll
    for (int o = 1; o <= 2; o <<= 1) {
        sum0 += __shfl_xor_sync(0xffffffffu, sum0, o);
        sum1 += __shfl_xor_sync(0xffffffffu, sum1, o);
    }
    float* sbuf = (float*)(sm + SUMO);
    __syncthreads();
    if (wn == 0 && (lane & 3) == 0) { sbuf[r0] = sum0; sbuf[r1] = sum1; }
    __syncthreads();
    if (wn == 1 && (lane & 3) == 0) {
        float t0 = sbuf[r0] + sum0, t1 = sbuf[r1] + sum1;
        sbuf[r0] = t0; sbuf[r1] = t1;
        g_sums[gq0 + r0] = t0;
        g_sums[gq0 + r1] = t1;
    }
    __syncthreads();

    // ---------------- O: reduce across the two kv-half warps, scale, store ----------------
    float* ob = (float*)(sm + OBUF);   // [64][64], reuses K/V staging space
    const int cc = (lane & 3) * 2;
    if (wn == 0) {
        #pragma unroll
        for (int nt = 0; nt < 8; ++nt) {
            ob[r0 * 64 + nt * 8 + cc]     = oacc[nt][0];
            ob[r0 * 64 + nt * 8 + cc + 1] = oacc[nt][1];
            ob[r1 * 64 + nt * 8 + cc]     = oacc[nt][2];
            ob[r1 * 64 + nt * 8 + cc + 1] = oacc[nt][3];
        }
    }
    __syncthreads();
    if (wn == 1) {
        float iv0 = 1.f / sbuf[r0], iv1 = 1.f / sbuf[r1];
        float* o0 = out_o + (gq0 + r0) * D;
        float* o1 = out_o + (gq0 + r1) * D;
        #pragma unroll
        for (int nt = 0; nt < 8; ++nt) {
            int c = nt * 8 + cc;
            *(float2*)(o0 + c) = make_float2((oacc[nt][0] + ob[r0 * 64 + c]) * iv0,
                                             (oacc[nt][1] + ob[r0 * 64 + c + 1]) * iv0);
            *(float2*)(o1 + c) = make_float2((oacc[nt][2] + ob[r1 * 64 + c]) * iv1,
                                             (oacc[nt][3] + ob[r1 * 64 + c + 1]) * iv1);
        }
    }
}

// ============ rescale: p = e * inv[row], in place (streaming) ============
__global__ void __launch_bounds__(256)
rescale_kernel(float* __restrict__ p)
{
    const int row = blockIdx.x * 2 + (threadIdx.x >> 7);
    const float inv = 1.f / g_sums[row];
    float4* pr = (float4*)(p + (size_t)row * S);
    const int c = threadIdx.x & 127;
    #pragma unroll
    for (int i = 0; i < 4; ++i) {
        float4 v = __ldcs(pr + c + i * 128);
        v.x *= inv; v.y *= inv; v.z *= inv; v.w *= inv;
        __stcs(pr + c + i * 128, v);
    }
}

extern "C" void kernel_launch(void* const* d_in, const int* in_sizes, int n_in,
                              void* d_out, int out_size)
{
    const float* Q     = (const float*)d_in[0];
    const float* K     = (const float*)d_in[1];
    const float* V     = (const float*)d_in[2];
    const int*   mask  = (const int*)d_in[3];
    const float* decay = (const float*)d_in[4];

    float* out_o = (float*)d_out;
    float* out_p = (float*)d_out + (size_t)BH * S * D;

    cudaFuncSetAttribute(fused_kernel, cudaFuncAttributeMaxDynamicSharedMemorySize, (int)SMEM_F);

    pack_mask_kernel<<<2 * S * S / 256 / 32 * 32, 256>>>(mask);   // 32768 blocks
    fused_kernel<<<BH * (S / 64), 256, SMEM_F>>>(Q, K, V, decay, out_p, out_o);
    rescale_kernel<<<BH * S / 2, 256>>>(out_p);
}

// round 16
// speedup vs baseline: 1.2593x; 1.0366x over previous
#include <cuda_runtime.h>
#include <cuda_bf16.h>
#include <cstdint>

constexpr int BH = 16, S = 2048, D = 64;

__device__ float g_sums[BH * S];
__device__ uint32_t g_maskbits[2 * S * (S / 32)];   // 1 MB packed mask

// ---------------- helpers ----------------
__device__ __forceinline__ uint32_t smem_u32(const void* p) {
    uint32_t a;
    asm("{ .reg .u64 t; cvta.to.shared.u64 t, %1; cvt.u32.u64 %0, t; }" : "=r"(a) : "l"(p));
    return a;
}
__device__ __forceinline__ uint32_t pk(float a, float b) {
    __nv_bfloat162 t = __floats2bfloat162_rn(a, b);
    return *reinterpret_cast<uint32_t*>(&t);
}
__device__ __forceinline__ float hi_bf(float x) {
    return __bfloat162float(__float2bfloat16_rn(x));
}
__device__ __forceinline__ uint32_t sw128(uint32_t b) { return b ^ ((b >> 3) & 0x70); }

__device__ __forceinline__ void ldsm4(uint32_t a, uint32_t r[4]) {
    asm volatile("ldmatrix.sync.aligned.m8n8.x4.shared.b16 {%0,%1,%2,%3}, [%4];"
                 : "=r"(r[0]), "=r"(r[1]), "=r"(r[2]), "=r"(r[3]) : "r"(a));
}
__device__ __forceinline__ void ldsm4t(uint32_t a, uint32_t r[4]) {
    asm volatile("ldmatrix.sync.aligned.m8n8.x4.trans.shared.b16 {%0,%1,%2,%3}, [%4];"
                 : "=r"(r[0]), "=r"(r[1]), "=r"(r[2]), "=r"(r[3]) : "r"(a));
}
__device__ __forceinline__ void mma16816(float c[4], const uint32_t a[4], uint32_t b0, uint32_t b1) {
    asm volatile(
        "mma.sync.aligned.m16n8k16.row.col.f32.bf16.bf16.f32 "
        "{%0,%1,%2,%3}, {%4,%5,%6,%7}, {%8,%9}, {%0,%1,%2,%3};"
        : "+f"(c[0]), "+f"(c[1]), "+f"(c[2]), "+f"(c[3])
        : "r"(a[0]), "r"(a[1]), "r"(a[2]), "r"(a[3]), "r"(b0), "r"(b1));
}
// streaming (evict-first) float2 store: e is not re-read within L2 lifetime
__device__ __forceinline__ void stcs2(float* p, float a, float b) {
    asm volatile("st.global.cs.v2.f32 [%0], {%1, %2};" :: "l"(p), "f"(a), "f"(b) : "memory");
}

// smem map (bytes): Qhi 8K, Qlo 8K, Khi 16K, Klo 16K, Vhi 16K, Vlo 16K, sums 256
constexpr int QHI = 0, QLO = 8192, KHI = 16384, KLO = 32768,
              VHI = 49152, VLO = 65536, SUMO = 81920, OBUF = 16384;
constexpr size_t SMEM_F = 82432;

// ============ pack mask int32 -> bits (bandwidth-bound version) ============
// Each warp packs 512 contiguous ints per iteration via 4 coalesced per-lane
// loads (MLP=4) + 4 ballots; 4 iterations -> 2048 ints per warp.
__global__ void __launch_bounds__(256)
pack_mask_kernel(const int* __restrict__ mask)
{
    const int lane = threadIdx.x & 31;
    const int warp_g = (blockIdx.x * 256 + threadIdx.x) >> 5;   // 16384 warps
    const size_t base = (size_t)warp_g * 512;
    #pragma unroll
    for (int i = 0; i < 4; ++i) {
        const int* src = mask + base + i * 128;
        int v0 = __ldcs(src + lane);
        int v1 = __ldcs(src + 32 + lane);
        int v2 = __ldcs(src + 64 + lane);
        int v3 = __ldcs(src + 96 + lane);
        uint32_t w0 = __ballot_sync(0xffffffffu, v0 != 0);
        uint32_t w1 = __ballot_sync(0xffffffffu, v1 != 0);
        uint32_t w2 = __ballot_sync(0xffffffffu, v2 != 0);
        uint32_t w3 = __ballot_sync(0xffffffffu, v3 != 0);
        if (lane == 0) {
            uint32_t* dst = g_maskbits + (base >> 5) + i * 4;
            *(uint4*)dst = make_uint4(w0, w1, w2, w3);
        }
    }
}

// ==== fused: e = exp(clip/mask/decay(QK^T)) -> p region, O = (e@V)*inv ====
__global__ void __launch_bounds__(256, 2)
fused_kernel(const float* __restrict__ Q, const float* __restrict__ K,
             const float* __restrict__ V, const float* __restrict__ decay,
             float* __restrict__ e_out, float* __restrict__ out_o)
{
    extern __shared__ char sm[];
    const uint32_t sb = smem_u32(sm);
    const int t = threadIdx.x, wid = t >> 5, lane = t & 31;
    const int bid = blockIdx.x, bh = bid >> 5, q0 = (bid & 31) * 64, b = bh >> 3;

    // stage Q tile (pre-scaled 1/8) -> hi/lo bf16
    {
        const float4* Qp = (const float4*)(Q + ((size_t)bh * S + q0) * D);
        #pragma unroll
        for (int i = 0; i < 4; ++i) {
            int idx = t + i * 256, r = idx >> 4, c4 = (idx & 15) * 4;
            float4 v = Qp[idx];
            float x0 = v.x * 0.125f, x1 = v.y * 0.125f, x2 = v.z * 0.125f, x3 = v.w * 0.125f;
            float h0 = hi_bf(x0), h1 = hi_bf(x1), h2 = hi_bf(x2), h3 = hi_bf(x3);
            uint32_t o = sw128((uint32_t)(r * 128 + c4 * 2));
            *(uint2*)(sm + QHI + o) = make_uint2(pk(h0, h1), pk(h2, h3));
            *(uint2*)(sm + QLO + o) = make_uint2(pk(x0 - h0, x1 - h1), pk(x2 - h2, x3 - h3));
        }
    }

    const int wm = wid & 3;        // m16 block (q rows)
    const int wn = wid >> 2;       // 64-col half of the 128-col kv tile
    const int r0 = wm * 16 + (lane >> 2), r1 = r0 + 8;
    const size_t gq0 = (size_t)bh * S + q0;
    const float* drow0 = decay + (gq0 + r0) * S;
    const float* drow1 = decay + (gq0 + r1) * S;
    const uint32_t* mbr0 = g_maskbits + ((size_t)b * S + q0 + r0) * (S / 32);
    const uint32_t* mbr1 = g_maskbits + ((size_t)b * S + q0 + r1) * (S / 32);
    float*       erow0 = e_out + (gq0 + r0) * S;
    float*       erow1 = e_out + (gq0 + r1) * S;
    float sum0 = 0.f, sum1 = 0.f;

    float oacc[8][4];
    #pragma unroll
    for (int n = 0; n < 8; ++n)
        #pragma unroll
        for (int j = 0; j < 4; ++j) oacc[n][j] = 0.f;

    for (int it = 0; it < 16; ++it) {
        __syncthreads();
        // stage K,V tiles [128 kv][64 d] -> hi/lo bf16
        {
            const float4* Kp = (const float4*)(K + ((size_t)bh * S + it * 128) * D);
            const float4* Vp = (const float4*)(V + ((size_t)bh * S + it * 128) * D);
            #pragma unroll
            for (int i = 0; i < 8; ++i) {
                int idx = t + i * 256, r = idx >> 4, c4 = (idx & 15) * 4;
                uint32_t o = sw128((uint32_t)(r * 128 + c4 * 2));
                float4 v = Kp[idx];
                float h0 = hi_bf(v.x), h1 = hi_bf(v.y), h2 = hi_bf(v.z), h3 = hi_bf(v.w);
                *(uint2*)(sm + KHI + o) = make_uint2(pk(h0, h1), pk(h2, h3));
                *(uint2*)(sm + KLO + o) = make_uint2(pk(v.x - h0, v.y - h1), pk(v.z - h2, v.w - h3));
                float4 w = Vp[idx];
                float g0 = hi_bf(w.x), g1 = hi_bf(w.y), g2 = hi_bf(w.z), g3 = hi_bf(w.w);
                *(uint2*)(sm + VHI + o) = make_uint2(pk(g0, g1), pk(g2, g3));
                *(uint2*)(sm + VLO + o) = make_uint2(pk(w.x - g0, w.y - g1), pk(w.z - g2, w.w - g3));
            }
        }

        // prefetch decay + packed mask words for this tile (consumed post-MMA)
        const int cb0 = it * 128 + wn * 64 + (lane & 3) * 2;
        const int wbase = (it * 128 + wn * 64) >> 5;     // 2 words per row cover 64 cols
        const uint32_t w00 = mbr0[wbase], w01 = mbr0[wbase + 1];
        const uint32_t w10 = mbr1[wbase], w11 = mbr1[wbase + 1];
        float dpr[32];
        #pragma unroll
        for (int nt = 0; nt < 8; ++nt) {
            const int c = cb0 + nt * 8;
            float2 d0 = *(const float2*)(drow0 + c);
            float2 d1 = *(const float2*)(drow1 + c);
            dpr[nt * 4 + 0] = d0.x; dpr[nt * 4 + 1] = d0.y;
            dpr[nt * 4 + 2] = d1.x; dpr[nt * 4 + 3] = d1.y;
        }
        __syncthreads();

        // ---------------- S = QK^T (3-split) ----------------
        float acc[8][4];
        #pragma unroll
        for (int n = 0; n < 8; ++n)
            #pragma unroll
            for (int j = 0; j < 4; ++j) acc[n][j] = 0.f;

        #pragma unroll
        for (int kc4 = 0; kc4 < 4; ++kc4) {
            const int kc = kc4 * 16;
            const uint32_t arow = (uint32_t)((wm * 16 + (lane & 15)) * 128 +
                                             (kc + ((lane >> 4) & 1) * 8) * 2);
            uint32_t ah[4], al[4];
            ldsm4(sb + QHI + sw128(arow), ah);
            #pragma unroll
            for (int p = 0; p < 4; ++p) {
                uint32_t brow = (uint32_t)((wn * 64 + p * 16 + (lane & 7) + (lane >> 4) * 8) * 128 +
                                           (kc + ((lane >> 3) & 1) * 8) * 2);
                uint32_t bo = sw128(brow);
                uint32_t bb[4];
                ldsm4(sb + KHI + bo, bb);
                mma16816(acc[2 * p], ah, bb[0], bb[1]);
                mma16816(acc[2 * p + 1], ah, bb[2], bb[3]);
                ldsm4(sb + KLO + bo, bb);
                mma16816(acc[2 * p], ah, bb[0], bb[1]);
                mma16816(acc[2 * p + 1], ah, bb[2], bb[3]);
            }
            ldsm4(sb + QLO + sw128(arow), al);
            #pragma unroll
            for (int p = 0; p < 4; ++p) {
                uint32_t brow = (uint32_t)((wn * 64 + p * 16 + (lane & 7) + (lane >> 4) * 8) * 128 +
                                           (kc + ((lane >> 3) & 1) * 8) * 2);
                uint32_t bb[4];
                ldsm4(sb + KHI + sw128(brow), bb);
                mma16816(acc[2 * p], al, bb[0], bb[1]);
                mma16816(acc[2 * p + 1], al, bb[2], bb[3]);
            }
        }

        // ---------------- epilogue: clip/mask/decay/exp (bit-packed mask) ----------------
        #pragma unroll
        for (int nt = 0; nt < 8; ++nt) {
            const int c = cb0 + nt * 8;
            const int sh = (lane & 3) * 2 + (nt & 3) * 8;   // bit pos within word
            const uint32_t wr0 = (nt < 4) ? w00 : w01;
            const uint32_t wr1 = (nt < 4) ? w10 : w11;
            float s00 = fminf(fmaxf(acc[nt][0], 1e-9f), 1e9f);
            float s01 = fminf(fmaxf(acc[nt][1], 1e-9f), 1e9f);
            float s10 = fminf(fmaxf(acc[nt][2], 1e-9f), 1e9f);
            float s11 = fminf(fmaxf(acc[nt][3], 1e-9f), 1e9f);
            s00 = (wr0 >> sh & 1u)       ? s00 : -1e9f;
            s01 = (wr0 >> (sh + 1) & 1u) ? s01 : -1e9f;
            s10 = (wr1 >> sh & 1u)       ? s10 : -1e9f;
            s11 = (wr1 >> (sh + 1) & 1u) ? s11 : -1e9f;
            float e00 = __expf(s00 * dpr[nt * 4 + 0]), e01 = __expf(s01 * dpr[nt * 4 + 1]);
            float e10 = __expf(s10 * dpr[nt * 4 + 2]), e11 = __expf(s11 * dpr[nt * 4 + 3]);
            sum0 += e00 + e01;
            sum1 += e10 + e11;
            stcs2(erow0 + c, e00, e01);
            stcs2(erow1 + c, e10, e11);
            acc[nt][0] = e00; acc[nt][1] = e01; acc[nt][2] = e10; acc[nt][3] = e11;
        }

        // ---------------- PV: O += e @ V (A recycled from accumulators) ----------------
        #pragma unroll
        for (int kc = 0; kc < 4; ++kc) {
            float h00 = hi_bf(acc[2*kc][0]),   h01 = hi_bf(acc[2*kc][1]);
            float h02 = hi_bf(acc[2*kc][2]),   h03 = hi_bf(acc[2*kc][3]);
            float h10 = hi_bf(acc[2*kc+1][0]), h11 = hi_bf(acc[2*kc+1][1]);
            float h12 = hi_bf(acc[2*kc+1][2]), h13 = hi_bf(acc[2*kc+1][3]);
            uint32_t ah[4] = { pk(h00, h01), pk(h02, h03), pk(h10, h11), pk(h12, h13) };
            uint32_t al[4] = { pk(acc[2*kc][0] - h00,   acc[2*kc][1] - h01),
                               pk(acc[2*kc][2] - h02,   acc[2*kc][3] - h03),
                               pk(acc[2*kc+1][0] - h10, acc[2*kc+1][1] - h11),
                               pk(acc[2*kc+1][2] - h12, acc[2*kc+1][3] - h13) };
            #pragma unroll
            for (int p2 = 0; p2 < 4; ++p2) {
                uint32_t brow = (uint32_t)((wn * 64 + kc * 16 + (lane & 7) + ((lane >> 3) & 1) * 8) * 128 +
                                           (p2 * 16 + (lane >> 4) * 8) * 2);
                uint32_t bo = sw128(brow);
                uint32_t bb[4];
                ldsm4t(sb + VHI + bo, bb);
                mma16816(oacc[2 * p2],     ah, bb[0], bb[1]);
                mma16816(oacc[2 * p2 + 1], ah, bb[2], bb[3]);
                mma16816(oacc[2 * p2],     al, bb[0], bb[1]);
                mma16816(oacc[2 * p2 + 1], al, bb[2], bb[3]);
                ldsm4t(sb + VLO + bo, bb);
                mma16816(oacc[2 * p2],     ah, bb[0], bb[1]);
                mma16816(oacc[2 * p2 + 1], ah, bb[2], bb[3]);
            }
        }
    }

    // ---------------- row sums -> g_sums ----------------
    #pragma unroll
    for (int o = 1; o <= 2; o <<= 1) {
        sum0 += __shfl_xor_sync(0xffffffffu, sum0, o);
        sum1 += __shfl_xor_sync(0xffffffffu, sum1, o);
    }
    float* sbuf = (float*)(sm + SUMO);
    __syncthreads();
    if (wn == 0 && (lane & 3) == 0) { sbuf[r0] = sum0; sbuf[r1] = sum1; }
    __syncthreads();
    if (wn == 1 && (lane & 3) == 0) {
        float t0 = sbuf[r0] + sum0, t1 = sbuf[r1] + sum1;
        sbuf[r0] = t0; sbuf[r1] = t1;
        g_sums[gq0 + r0] = t0;
        g_sums[gq0 + r1] = t1;
    }
    __syncthreads();

    // ---------------- O: reduce across the two kv-half warps, scale, store ----------------
    float* ob = (float*)(sm + OBUF);   // [64][64], reuses K/V staging space
    const int cc = (lane & 3) * 2;
    if (wn == 0) {
        #pragma unroll
        for (int nt = 0; nt < 8; ++nt) {
            ob[r0 * 64 + nt * 8 + cc]     = oacc[nt][0];
            ob[r0 * 64 + nt * 8 + cc + 1] = oacc[nt][1];
            ob[r1 * 64 + nt * 8 + cc]     = oacc[nt][2];
            ob[r1 * 64 + nt * 8 + cc + 1] = oacc[nt][3];
        }
    }
    __syncthreads();
    if (wn == 1) {
        float iv0 = 1.f / sbuf[r0], iv1 = 1.f / sbuf[r1];
        float* o0 = out_o + (gq0 + r0) * D;
        float* o1 = out_o + (gq0 + r1) * D;
        #pragma unroll
        for (int nt = 0; nt < 8; ++nt) {
            int c = nt * 8 + cc;
            *(float2*)(o0 + c) = make_float2((oacc[nt][0] + ob[r0 * 64 + c]) * iv0,
                                             (oacc[nt][1] + ob[r0 * 64 + c + 1]) * iv0);
            *(float2*)(o1 + c) = make_float2((oacc[nt][2] + ob[r1 * 64 + c]) * iv1,
                                             (oacc[nt][3] + ob[r1 * 64 + c + 1]) * iv1);
        }
    }
}

// ============ rescale: p = e * inv[row], in place (streaming) ============
__global__ void __launch_bounds__(256)
rescale_kernel(float* __restrict__ p)
{
    const int row = blockIdx.x * 2 + (threadIdx.x >> 7);
    const float inv = 1.f / g_sums[row];
    float4* pr = (float4*)(p + (size_t)row * S);
    const int c = threadIdx.x & 127;
    #pragma unroll
    for (int i = 0; i < 4; ++i) {
        float4 v = __ldcs(pr + c + i * 128);
        v.x *= inv; v.y *= inv; v.z *= inv; v.w *= inv;
        __stcs(pr + c + i * 128, v);
    }
}

extern "C" void kernel_launch(void* const* d_in, const int* in_sizes, int n_in,
                              void* d_out, int out_size)
{
    const float* Q     = (const float*)d_in[0];
    const float* K     = (const float*)d_in[1];
    const float* V     = (const float*)d_in[2];
    const int*   mask  = (const int*)d_in[3];
    const float* decay = (const float*)d_in[4];

    float* out_o = (float*)d_out;
    float* out_p = (float*)d_out + (size_t)BH * S * D;

    cudaFuncSetAttribute(fused_kernel, cudaFuncAttributeMaxDynamicSharedMemorySize, (int)SMEM_F);

    pack_mask_kernel<<<2048, 256>>>(mask);               // 16384 warps x 512 ints
    fused_kernel<<<BH * (S / 64), 256, SMEM_F>>>(Q, K, V, decay, out_p, out_o);
    rescale_kernel<<<BH * S / 2, 256>>>(out_p);
}